// round 16
// baseline (speedup 1.0000x reference)
#include <cuda_runtime.h>
#include <cuda_fp16.h>
#include <cstdint>
#include <cstring>

#define T_STEPS 8
#define NBLK 2048
#define THREADS 256

// per-M-group named barrier: warps 0-3 = group 0 (rows 0-31), warps 4-7 = group 1
#define GBAR(gid) asm volatile("bar.sync %0, 128;" :: "r"((gid) + 1) : "memory")

// layer-1 h sequence, fp16: [blk][t][2048 u32] (word w: m=w>>5, j=(w&31)*2)
__device__ uint32_t g_h1[(size_t)NBLK * T_STEPS * 2048];

// ---------------- kernel1 smem layout (bytes) ----------------
#define K1_BX    0         // [256][40] fp16 (80B rows): cols0-5 Wx, rest 0
#define K1_W1    20480     // Whh0 [256][72] (144B rows)
#define K1_X0    57344     // x tile buf0 [64][40]
#define K1_X1    62464     // x tile buf1
#define K1_H0    67584     // h1 buf0 [64][72]
#define K1_H1    76800     // h1 buf1
#define K1_BIAS  86016     // fp32 [256]
#define K1_SMEM  87040

// ---------------- kernel2 smem layout ----------------
#define K2_W2    0         // [Wih1|Whh1] [256][136] (272B rows)
#define K2_H1A   69632     // h1 buf0 [64][72]
#define K2_H1B   78848
#define K2_H2A   88064     // h2 buf0
#define K2_H2B   97280
#define K2_BIAS  106496    // fp32 [256]
#define K2_WFC   107520    // fp32 [64]
#define K2_SCR   107776    // fp32 [64]
#define K2_SMEM  108032

__device__ __forceinline__ uint32_t smem_u32(const void* p) {
    uint32_t a;
    asm("{ .reg .u64 t; cvta.to.shared.u64 t, %1; cvt.u32.u64 %0, t; }" : "=r"(a) : "l"(p));
    return a;
}
__device__ __forceinline__ void mma16816(float* d, const uint32_t* a, const uint32_t* b) {
    asm volatile("mma.sync.aligned.m16n8k16.row.col.f32.f16.f16.f32 "
        "{%0,%1,%2,%3},{%4,%5,%6,%7},{%8,%9},{%0,%1,%2,%3};"
        : "+f"(d[0]), "+f"(d[1]), "+f"(d[2]), "+f"(d[3])
        : "r"(a[0]), "r"(a[1]), "r"(a[2]), "r"(a[3]), "r"(b[0]), "r"(b[1]));
}
__device__ __forceinline__ void ldsm_x4(uint32_t* r, uint32_t addr) {
    asm volatile("ldmatrix.sync.aligned.m8n8.x4.shared.b16 {%0,%1,%2,%3}, [%4];"
        : "=r"(r[0]), "=r"(r[1]), "=r"(r[2]), "=r"(r[3]) : "r"(addr));
}
__device__ __forceinline__ float tanha(float x) {
    float r; asm("tanh.approx.f32 %0, %1;" : "=f"(r) : "f"(x)); return r;
}
__device__ __forceinline__ float sigf(float x) { return fmaf(tanha(0.5f * x), 0.5f, 0.5f); }

// ============================ kernel 1: layer 1 ============================
__global__ void __launch_bounds__(THREADS, 2) lstm_l1(
    const float* __restrict__ x,
    const float* __restrict__ Wih0, const float* __restrict__ Whh0,
    const float* __restrict__ bih0, const float* __restrict__ bhh0)
{
    extern __shared__ char sm[];
    const int tid = threadIdx.x;

    for (int i = tid; i < K1_SMEM / 4; i += THREADS) ((uint32_t*)sm)[i] = 0;
    __syncthreads();

    for (int idx = tid; idx < 1536; idx += THREADS) {
        int r = idx / 6, i = idx - r * 6;
        *(__half*)(sm + K1_BX + r * 80 + i * 2) = __float2half(Wih0[idx]);
    }
    for (int idx = tid; idx < 16384; idx += THREADS) {
        int r = idx >> 6, k = idx & 63;
        *(__half*)(sm + K1_W1 + r * 144 + k * 2) = __float2half(Whh0[idx]);
    }
    if (tid < 256) ((float*)(sm + K1_BIAS))[tid] = bih0[tid] + bhh0[tid];

    const int l = tid & 31, w = tid >> 5, mw = w >> 2, nw = w & 3;
    const int g = tid >> 7;            // M-group (== mw)
    const int lt = tid & 127;          // thread id within group
    const int m0 = mw * 32;
    const uint32_t sb = smem_u32(sm);
    const int rowA = l & 15;
    const int colA = (l & 16) ? 16 : 0;
    const int rowB2 = (l & 7) + ((l >> 4) & 1) * 64;
    const int colB2 = ((l >> 3) & 1) * 16;
    const size_t gb = (size_t)blockIdx.x * 64;
    const float* biasp = (const float*)(sm + K1_BIAS);

    float c[16];
#pragma unroll
    for (int i = 0; i < 16; i++) c[i] = 0.0f;

    // prefetch + stage x(0) into X0 (per-group rows: g*32 + lt)
    float pfx[6];
    const int xrow_idx = g * 32 + lt;  // valid row if lt<32
    const float* xrow_g = x + (gb + xrow_idx) * 48;
    if (lt < 32) {
#pragma unroll
        for (int i = 0; i < 6; i++) pfx[i] = xrow_g[i];
        char* xrow = sm + K1_X0 + xrow_idx * 80;
#pragma unroll
        for (int i = 0; i < 6; i++)
            *(__half*)(xrow + i * 2) = __float2half(pfx[i]);
    }
    __syncthreads();

    const uint32_t XB[2] = { sb + K1_X0, sb + K1_X1 };
    const uint32_t HB[2] = { sb + K1_H0, sb + K1_H1 };
    const char*    HBc[2] = { sm + K1_H0, sm + K1_H1 };
    char*          HBw[2] = { sm + K1_H0, sm + K1_H1 };

    for (int t = 0; t < T_STEPS; t++) {
        const int cur = t & 1, nxt = cur ^ 1;

        // prefetch x(t+1)
        if (lt < 32 && t < T_STEPS - 1) {
#pragma unroll
            for (int i = 0; i < 6; i++) pfx[i] = xrow_g[(t + 1) * 6 + i];
        }
        // pack h(t-1) -> gmem, own group's rows only (words g*1024 .. g*1024+1023)
        if (t > 0) {
            uint32_t* gdst = g_h1 + ((size_t)blockIdx.x * T_STEPS + (t - 1)) * 2048;
#pragma unroll
            for (int q = 0; q < 2; q++) {
                int iu = g * 1024 + q * 512 + lt * 4;
                int m = iu >> 5, jh = (iu & 31) * 2;
                *(uint4*)(gdst + iu) = *(const uint4*)(HBc[cur] + m * 144 + jh * 2);
            }
        }

        // ---- MMA phase ----
        float d[2][2][4][4];
#pragma unroll
        for (int p = 0; p < 2; p++) {
            const int js = nw * 16 + p * 8;
#pragma unroll
            for (int gg2 = 0; gg2 < 4; gg2++) {
                float2 bv = *(const float2*)(biasp + gg2 * 64 + js + 2 * (l & 3));
#pragma unroll
                for (int mt = 0; mt < 2; mt++) {
                    d[p][mt][gg2][0] = bv.x; d[p][mt][gg2][1] = bv.y;
                    d[p][mt][gg2][2] = bv.x; d[p][mt][gg2][3] = bv.y;
                }
            }
        }
        // x-part: one K=16 chunk
        {
            uint32_t ah0[4], ah1[4];
            ldsm_x4(ah0, XB[cur] + (uint32_t)(m0 + rowA) * 80 + colA);
            ldsm_x4(ah1, XB[cur] + (uint32_t)(m0 + 16 + rowA) * 80 + colA);
#pragma unroll
            for (int p = 0; p < 2; p++) {
                const int js = nw * 16 + p * 8;
                uint32_t b01[4], b23[4];
                ldsm_x4(b01, sb + K1_BX + (uint32_t)(js + rowB2) * 80 + colB2);
                ldsm_x4(b23, sb + K1_BX + (uint32_t)(128 + js + rowB2) * 80 + colB2);
                mma16816(d[p][0][0], ah0, b01);     mma16816(d[p][0][1], ah0, b01 + 2);
                mma16816(d[p][0][2], ah0, b23);     mma16816(d[p][0][3], ah0, b23 + 2);
                mma16816(d[p][1][0], ah1, b01);     mma16816(d[p][1][1], ah1, b01 + 2);
                mma16816(d[p][1][2], ah1, b23);     mma16816(d[p][1][3], ah1, b23 + 2);
            }
        }
        // h-part: K=64
#pragma unroll
        for (int kt = 0; kt < 4; kt++) {
            const int k0 = kt * 16;
            uint32_t ah0[4], ah1[4];
            ldsm_x4(ah0, HB[cur] + (uint32_t)(m0 + rowA) * 144 + k0 * 2 + colA);
            ldsm_x4(ah1, HB[cur] + (uint32_t)(m0 + 16 + rowA) * 144 + k0 * 2 + colA);
#pragma unroll
            for (int p = 0; p < 2; p++) {
                const int js = nw * 16 + p * 8;
                uint32_t b01[4], b23[4];
                ldsm_x4(b01, sb + K1_W1 + (uint32_t)(js + rowB2) * 144 + k0 * 2 + colB2);
                ldsm_x4(b23, sb + K1_W1 + (uint32_t)(128 + js + rowB2) * 144 + k0 * 2 + colB2);
                mma16816(d[p][0][0], ah0, b01);     mma16816(d[p][0][1], ah0, b01 + 2);
                mma16816(d[p][0][2], ah0, b23);     mma16816(d[p][0][3], ah0, b23 + 2);
                mma16816(d[p][1][0], ah1, b01);     mma16816(d[p][1][1], ah1, b01 + 2);
                mma16816(d[p][1][2], ah1, b23);     mma16816(d[p][1][3], ah1, b23 + 2);
            }
        }

        // stage x(t+1) into the other buffer (own group's rows)
        if (lt < 32 && t < T_STEPS - 1) {
            char* xrow = (nxt ? sm + K1_X1 : sm + K1_X0) + xrow_idx * 80;
#pragma unroll
            for (int i = 0; i < 6; i++)
                *(__half*)(xrow + i * 2) = __float2half(pfx[i]);
        }

        // ---- epilogue: write h(t) into HB[nxt] (own group's rows) ----
#pragma unroll
        for (int p = 0; p < 2; p++) {
            const int js = nw * 16 + p * 8;
#pragma unroll
            for (int mt = 0; mt < 2; mt++)
#pragma unroll
            for (int rr = 0; rr < 2; rr++) {
                float hv[2];
#pragma unroll
                for (int jj = 0; jj < 2; jj++) {
                    int reg = rr * 2 + jj;
                    float gi = d[p][mt][0][reg];
                    float gf = d[p][mt][1][reg];
                    float gg = d[p][mt][2][reg];
                    float go = d[p][mt][3][reg];
                    int ci = ((p * 2 + mt) * 2 + rr) * 2 + jj;
                    float cc = sigf(gf) * c[ci] + sigf(gi) * tanha(gg);
                    c[ci] = cc;
                    hv[jj] = sigf(go) * tanha(cc);
                }
                int r = m0 + 16 * mt + (l >> 2) + 8 * rr;
                int j0 = js + 2 * (l & 3);
                *(__half2*)(HBw[nxt] + r * 144 + j0 * 2) =
                    __halves2half2(__float2half(hv[0]), __float2half(hv[1]));
            }
        }
        GBAR(g);   // only this M-group needs to agree
    }

    // final h(7) pack: needs both groups' rows visible -> full sync
    __syncthreads();
    {
        uint32_t* gdst = g_h1 + ((size_t)blockIdx.x * T_STEPS + 7) * 2048;
#pragma unroll
        for (int q = 0; q < 2; q++) {
            int iu = q * 1024 + tid * 4;
            int m = iu >> 5, jh = (iu & 31) * 2;
            *(uint4*)(gdst + iu) = *(const uint4*)(HBc[0] + m * 144 + jh * 2);
        }
    }
}

// ============================ kernel 2: layer 2 + FC ============================
__global__ void __launch_bounds__(THREADS, 2) lstm_l2(
    const float* __restrict__ Wih1, const float* __restrict__ Whh1,
    const float* __restrict__ bih1, const float* __restrict__ bhh1,
    const float* __restrict__ Wfc, const float* __restrict__ bfc,
    float* __restrict__ out)
{
    extern __shared__ char sm[];
    const int tid = threadIdx.x;

    for (int i = tid; i < K2_SMEM / 4; i += THREADS) ((uint32_t*)sm)[i] = 0;
    __syncthreads();

    for (int idx = tid; idx < 16384; idx += THREADS) {
        int r = idx >> 6, k = idx & 63;
        *(__half*)(sm + K2_W2 + r * 272 + k * 2) = __float2half(Wih1[idx]);
        *(__half*)(sm + K2_W2 + r * 272 + (64 + k) * 2) = __float2half(Whh1[idx]);
    }
    if (tid < 256) ((float*)(sm + K2_BIAS))[tid] = bih1[tid] + bhh1[tid];
    if (tid < 64)  ((float*)(sm + K2_WFC))[tid] = Wfc[tid];

    const int l = tid & 31, w = tid >> 5, mw = w >> 2, nw = w & 3;
    const int g = tid >> 7;
    const int lt = tid & 127;
    const int m0 = mw * 32;
    const uint32_t sb = smem_u32(sm);
    const int rowA = l & 15;
    const int colA = (l & 16) ? 16 : 0;
    const int rowB2 = (l & 7) + ((l >> 4) & 1) * 64;
    const int colB2 = ((l >> 3) & 1) * 16;
    const size_t gb = (size_t)blockIdx.x * 64;
    const float* biasp = (const float*)(sm + K2_BIAS);
    const float* wfcp  = (const float*)(sm + K2_WFC);
    float* scr = (float*)(sm + K2_SCR);

    float c[16];
#pragma unroll
    for (int i = 0; i < 16; i++) c[i] = 0.0f;

    const uint32_t* gsrc_base = g_h1 + (size_t)blockIdx.x * T_STEPS * 2048;

    // prefetch + stage h1(0) into H1A (own group's words)
    uint4 pf[2];
#pragma unroll
    for (int q = 0; q < 2; q++)
        pf[q] = *(const uint4*)(gsrc_base + g * 1024 + q * 512 + lt * 4);
#pragma unroll
    for (int q = 0; q < 2; q++) {
        int iu = g * 1024 + q * 512 + lt * 4;
        int m = iu >> 5, jh = (iu & 31) * 2;
        *(uint4*)(sm + K2_H1A + m * 144 + jh * 2) = pf[q];
    }
    __syncthreads();

    const uint32_t H1B_[2] = { sb + K2_H1A, sb + K2_H1B };
    const uint32_t H2B_[2] = { sb + K2_H2A, sb + K2_H2B };
    char* H1w[2] = { sm + K2_H1A, sm + K2_H1B };
    char* H2w[2] = { sm + K2_H2A, sm + K2_H2B };

    for (int t = 0; t < T_STEPS; t++) {
        const int cur = t & 1, nxt = cur ^ 1;

        // prefetch h1(t+1) (own group's words)
        if (t < T_STEPS - 1) {
            const uint32_t* gsrc = gsrc_base + (size_t)(t + 1) * 2048;
#pragma unroll
            for (int q = 0; q < 2; q++)
                pf[q] = *(const uint4*)(gsrc + g * 1024 + q * 512 + lt * 4);
        }

        // ---- MMA phase ----
        float d[2][2][4][4];
#pragma unroll
        for (int p = 0; p < 2; p++) {
            const int js = nw * 16 + p * 8;
#pragma unroll
            for (int gg2 = 0; gg2 < 4; gg2++) {
                float2 bv = *(const float2*)(biasp + gg2 * 64 + js + 2 * (l & 3));
#pragma unroll
                for (int mt = 0; mt < 2; mt++) {
                    d[p][mt][gg2][0] = bv.x; d[p][mt][gg2][1] = bv.y;
                    d[p][mt][gg2][2] = bv.x; d[p][mt][gg2][3] = bv.y;
                }
            }
        }
#pragma unroll
        for (int kt = 0; kt < 8; kt++) {
            const int k0 = kt * 16;
            const uint32_t abase = (kt < 4) ? H1B_[cur] : H2B_[cur];
            const int ka = (kt < 4) ? k0 : (k0 - 64);
            uint32_t ah0[4], ah1[4];
            ldsm_x4(ah0, abase + (uint32_t)(m0 + rowA) * 144 + ka * 2 + colA);
            ldsm_x4(ah1, abase + (uint32_t)(m0 + 16 + rowA) * 144 + ka * 2 + colA);
#pragma unroll
            for (int p = 0; p < 2; p++) {
                const int js = nw * 16 + p * 8;
                uint32_t b01[4], b23[4];
                ldsm_x4(b01, sb + K2_W2 + (uint32_t)(js + rowB2) * 272 + k0 * 2 + colB2);
                ldsm_x4(b23, sb + K2_W2 + (uint32_t)(128 + js + rowB2) * 272 + k0 * 2 + colB2);
                mma16816(d[p][0][0], ah0, b01);     mma16816(d[p][0][1], ah0, b01 + 2);
                mma16816(d[p][0][2], ah0, b23);     mma16816(d[p][0][3], ah0, b23 + 2);
                mma16816(d[p][1][0], ah1, b01);     mma16816(d[p][1][1], ah1, b01 + 2);
                mma16816(d[p][1][2], ah1, b23);     mma16816(d[p][1][3], ah1, b23 + 2);
            }
        }

        // unpack prefetched h1(t+1) into H1[nxt] (own group's rows)
        if (t < T_STEPS - 1) {
#pragma unroll
            for (int q = 0; q < 2; q++) {
                int iu = g * 1024 + q * 512 + lt * 4;
                int m = iu >> 5, jh = (iu & 31) * 2;
                *(uint4*)(H1w[nxt] + m * 144 + jh * 2) = pf[q];
            }
        }

        // ---- epilogue: write h2(t) into H2[nxt]; FC on last step ----
#pragma unroll
        for (int p = 0; p < 2; p++) {
            const int js = nw * 16 + p * 8;
#pragma unroll
            for (int mt = 0; mt < 2; mt++)
#pragma unroll
            for (int rr = 0; rr < 2; rr++) {
                float hv[2];
#pragma unroll
                for (int jj = 0; jj < 2; jj++) {
                    int reg = rr * 2 + jj;
                    float gi = d[p][mt][0][reg];
                    float gf = d[p][mt][1][reg];
                    float gg = d[p][mt][2][reg];
                    float go = d[p][mt][3][reg];
                    int ci = ((p * 2 + mt) * 2 + rr) * 2 + jj;
                    float cc = sigf(gf) * c[ci] + sigf(gi) * tanha(gg);
                    c[ci] = cc;
                    hv[jj] = sigf(go) * tanha(cc);
                }
                int r = m0 + 16 * mt + (l >> 2) + 8 * rr;
                int j0 = js + 2 * (l & 3);
                *(__half2*)(H2w[nxt] + r * 144 + j0 * 2) =
                    __halves2half2(__float2half(hv[0]), __float2half(hv[1]));
                if (t == T_STEPS - 1)
                    atomicAdd(scr + r, hv[0] * wfcp[j0] + hv[1] * wfcp[j0 + 1]);
            }
        }
        GBAR(g);
    }

    __syncthreads();   // both groups' scr contributions visible
    if (tid < 64) out[gb + tid] = scr[tid] + bfc[0];
}

extern "C" void kernel_launch(void* const* d_in, const int* in_sizes, int n_in,
                              void* d_out, int out_size)
{
    const float* x    = (const float*)d_in[0];
    const float* Wih0 = (const float*)d_in[1];
    const float* Whh0 = (const float*)d_in[2];
    const float* bih0 = (const float*)d_in[3];
    const float* bhh0 = (const float*)d_in[4];
    const float* Wih1 = (const float*)d_in[5];
    const float* Whh1 = (const float*)d_in[6];
    const float* bih1 = (const float*)d_in[7];
    const float* bhh1 = (const float*)d_in[8];
    const float* Wfc  = (const float*)d_in[9];
    const float* bfc  = (const float*)d_in[10];
    float* out = (float*)d_out;

    cudaFuncSetAttribute(lstm_l1, cudaFuncAttributeMaxDynamicSharedMemorySize, K1_SMEM);
    cudaFuncSetAttribute(lstm_l2, cudaFuncAttributeMaxDynamicSharedMemorySize, K2_SMEM);

    lstm_l1<<<NBLK, THREADS, K1_SMEM>>>(x, Wih0, Whh0, bih0, bhh0);
    lstm_l2<<<NBLK, THREADS, K2_SMEM>>>(Wih1, Whh1, bih1, bhh1, Wfc, bfc, out);
}

// round 17
// speedup vs baseline: 1.0004x; 1.0004x over previous
#include <cuda_runtime.h>
#include <cuda_fp16.h>
#include <cstdint>
#include <cstring>

#define T_STEPS 8
#define NBLK 2048
#define THREADS 256

// per-M-group named barrier: warps 0-3 = group 0 (rows 0-31), warps 4-7 = group 1
#define GBAR(gid) asm volatile("bar.sync %0, 128;" :: "r"((gid) + 1) : "memory")

// layer-1 h sequence, fp16: [blk][t][2048 u32] (word w: m=w>>5, j=(w&31)*2)
__device__ uint32_t g_h1[(size_t)NBLK * T_STEPS * 2048];

// ---------------- kernel1 smem layout (bytes) ----------------
#define K1_BX    0         // [256][40] fp16 (80B rows): cols0-5 Wx, rest 0
#define K1_W1    20480     // Whh0 [256][72] (144B rows)
#define K1_X0    57344     // x tile buf0 [64][40]
#define K1_X1    62464     // x tile buf1
#define K1_H0    67584     // h1 buf0 [64][72]
#define K1_H1    76800     // h1 buf1
#define K1_BIAS  86016     // fp32 [256]
#define K1_SMEM  87040

// ---------------- kernel2 smem layout ----------------
#define K2_W2    0         // [Wih1|Whh1] [256][136] (272B rows)
#define K2_H1A   69632     // h1 buf0 [64][72]
#define K2_H1B   78848
#define K2_H2A   88064     // h2 buf0
#define K2_H2B   97280
#define K2_BIAS  106496    // fp32 [256]
#define K2_WFC   107520    // fp32 [64]
#define K2_SCR   107776    // fp32 [64]
#define K2_SMEM  108032

__device__ __forceinline__ uint32_t smem_u32(const void* p) {
    uint32_t a;
    asm("{ .reg .u64 t; cvta.to.shared.u64 t, %1; cvt.u32.u64 %0, t; }" : "=r"(a) : "l"(p));
    return a;
}
__device__ __forceinline__ void mma16816(float* d, const uint32_t* a, const uint32_t* b) {
    asm volatile("mma.sync.aligned.m16n8k16.row.col.f32.f16.f16.f32 "
        "{%0,%1,%2,%3},{%4,%5,%6,%7},{%8,%9},{%0,%1,%2,%3};"
        : "+f"(d[0]), "+f"(d[1]), "+f"(d[2]), "+f"(d[3])
        : "r"(a[0]), "r"(a[1]), "r"(a[2]), "r"(a[3]), "r"(b[0]), "r"(b[1]));
}
__device__ __forceinline__ void ldsm_x4(uint32_t* r, uint32_t addr) {
    asm volatile("ldmatrix.sync.aligned.m8n8.x4.shared.b16 {%0,%1,%2,%3}, [%4];"
        : "=r"(r[0]), "=r"(r[1]), "=r"(r[2]), "=r"(r[3]) : "r"(addr));
}
__device__ __forceinline__ float tanha(float x) {
    float r; asm("tanh.approx.f32 %0, %1;" : "=f"(r) : "f"(x)); return r;
}
__device__ __forceinline__ float sigf(float x) { return fmaf(tanha(0.5f * x), 0.5f, 0.5f); }

// ============================ kernel 1: layer 1 ============================
__global__ void __launch_bounds__(THREADS, 2) lstm_l1(
    const float* __restrict__ x,
    const float* __restrict__ Wih0, const float* __restrict__ Whh0,
    const float* __restrict__ bih0, const float* __restrict__ bhh0)
{
    extern __shared__ char sm[];
    const int tid = threadIdx.x;

    for (int i = tid; i < K1_SMEM / 4; i += THREADS) ((uint32_t*)sm)[i] = 0;
    __syncthreads();

    for (int idx = tid; idx < 1536; idx += THREADS) {
        int r = idx / 6, i = idx - r * 6;
        *(__half*)(sm + K1_BX + r * 80 + i * 2) = __float2half(Wih0[idx]);
    }
    for (int idx = tid; idx < 16384; idx += THREADS) {
        int r = idx >> 6, k = idx & 63;
        *(__half*)(sm + K1_W1 + r * 144 + k * 2) = __float2half(Whh0[idx]);
    }
    if (tid < 256) ((float*)(sm + K1_BIAS))[tid] = bih0[tid] + bhh0[tid];

    const int l = tid & 31, w = tid >> 5, mw = w >> 2, nw = w & 3;
    const int g = tid >> 7;            // M-group (== mw)
    const int lt = tid & 127;          // thread id within group
    const int m0 = mw * 32;
    const uint32_t sb = smem_u32(sm);
    const int rowA = l & 15;
    const int colA = (l & 16) ? 16 : 0;
    const int rowB2 = (l & 7) + ((l >> 4) & 1) * 64;
    const int colB2 = ((l >> 3) & 1) * 16;
    const size_t gb = (size_t)blockIdx.x * 64;
    const float* biasp = (const float*)(sm + K1_BIAS);

    float c[16];
#pragma unroll
    for (int i = 0; i < 16; i++) c[i] = 0.0f;

    // prefetch + stage x(0) into X0 (per-group rows: g*32 + lt)
    float pfx[6];
    const int xrow_idx = g * 32 + lt;  // valid row if lt<32
    const float* xrow_g = x + (gb + xrow_idx) * 48;
    if (lt < 32) {
#pragma unroll
        for (int i = 0; i < 6; i++) pfx[i] = xrow_g[i];
        char* xrow = sm + K1_X0 + xrow_idx * 80;
#pragma unroll
        for (int i = 0; i < 6; i++)
            *(__half*)(xrow + i * 2) = __float2half(pfx[i]);
    }
    __syncthreads();

    const uint32_t XB[2] = { sb + K1_X0, sb + K1_X1 };
    const uint32_t HB[2] = { sb + K1_H0, sb + K1_H1 };
    const char*    HBc[2] = { sm + K1_H0, sm + K1_H1 };
    char*          HBw[2] = { sm + K1_H0, sm + K1_H1 };

    for (int t = 0; t < T_STEPS; t++) {
        const int cur = t & 1, nxt = cur ^ 1;

        // prefetch x(t+1)
        if (lt < 32 && t < T_STEPS - 1) {
#pragma unroll
            for (int i = 0; i < 6; i++) pfx[i] = xrow_g[(t + 1) * 6 + i];
        }
        // pack h(t-1) -> gmem, own group's rows only (words g*1024 .. g*1024+1023)
        if (t > 0) {
            uint32_t* gdst = g_h1 + ((size_t)blockIdx.x * T_STEPS + (t - 1)) * 2048;
#pragma unroll
            for (int q = 0; q < 2; q++) {
                int iu = g * 1024 + q * 512 + lt * 4;
                int m = iu >> 5, jh = (iu & 31) * 2;
                *(uint4*)(gdst + iu) = *(const uint4*)(HBc[cur] + m * 144 + jh * 2);
            }
        }

        // ---- MMA phase ----
        float d[2][2][4][4];
#pragma unroll
        for (int p = 0; p < 2; p++) {
            const int js = nw * 16 + p * 8;
#pragma unroll
            for (int gg2 = 0; gg2 < 4; gg2++) {
                float2 bv = *(const float2*)(biasp + gg2 * 64 + js + 2 * (l & 3));
#pragma unroll
                for (int mt = 0; mt < 2; mt++) {
                    d[p][mt][gg2][0] = bv.x; d[p][mt][gg2][1] = bv.y;
                    d[p][mt][gg2][2] = bv.x; d[p][mt][gg2][3] = bv.y;
                }
            }
        }
        // x-part: one K=16 chunk
        {
            uint32_t ah0[4], ah1[4];
            ldsm_x4(ah0, XB[cur] + (uint32_t)(m0 + rowA) * 80 + colA);
            ldsm_x4(ah1, XB[cur] + (uint32_t)(m0 + 16 + rowA) * 80 + colA);
#pragma unroll
            for (int p = 0; p < 2; p++) {
                const int js = nw * 16 + p * 8;
                uint32_t b01[4], b23[4];
                ldsm_x4(b01, sb + K1_BX + (uint32_t)(js + rowB2) * 80 + colB2);
                ldsm_x4(b23, sb + K1_BX + (uint32_t)(128 + js + rowB2) * 80 + colB2);
                mma16816(d[p][0][0], ah0, b01);     mma16816(d[p][0][1], ah0, b01 + 2);
                mma16816(d[p][0][2], ah0, b23);     mma16816(d[p][0][3], ah0, b23 + 2);
                mma16816(d[p][1][0], ah1, b01);     mma16816(d[p][1][1], ah1, b01 + 2);
                mma16816(d[p][1][2], ah1, b23);     mma16816(d[p][1][3], ah1, b23 + 2);
            }
        }
        // h-part: K=64
#pragma unroll
        for (int kt = 0; kt < 4; kt++) {
            const int k0 = kt * 16;
            uint32_t ah0[4], ah1[4];
            ldsm_x4(ah0, HB[cur] + (uint32_t)(m0 + rowA) * 144 + k0 * 2 + colA);
            ldsm_x4(ah1, HB[cur] + (uint32_t)(m0 + 16 + rowA) * 144 + k0 * 2 + colA);
#pragma unroll
            for (int p = 0; p < 2; p++) {
                const int js = nw * 16 + p * 8;
                uint32_t b01[4], b23[4];
                ldsm_x4(b01, sb + K1_W1 + (uint32_t)(js + rowB2) * 144 + k0 * 2 + colB2);
                ldsm_x4(b23, sb + K1_W1 + (uint32_t)(128 + js + rowB2) * 144 + k0 * 2 + colB2);
                mma16816(d[p][0][0], ah0, b01);     mma16816(d[p][0][1], ah0, b01 + 2);
                mma16816(d[p][0][2], ah0, b23);     mma16816(d[p][0][3], ah0, b23 + 2);
                mma16816(d[p][1][0], ah1, b01);     mma16816(d[p][1][1], ah1, b01 + 2);
                mma16816(d[p][1][2], ah1, b23);     mma16816(d[p][1][3], ah1, b23 + 2);
            }
        }

        // stage x(t+1) into the other buffer (own group's rows)
        if (lt < 32 && t < T_STEPS - 1) {
            char* xrow = (nxt ? sm + K1_X1 : sm + K1_X0) + xrow_idx * 80;
#pragma unroll
            for (int i = 0; i < 6; i++)
                *(__half*)(xrow + i * 2) = __float2half(pfx[i]);
        }

        // ---- epilogue: write h(t) into HB[nxt] (own group's rows) ----
#pragma unroll
        for (int p = 0; p < 2; p++) {
            const int js = nw * 16 + p * 8;
#pragma unroll
            for (int mt = 0; mt < 2; mt++)
#pragma unroll
            for (int rr = 0; rr < 2; rr++) {
                float hv[2];
#pragma unroll
                for (int jj = 0; jj < 2; jj++) {
                    int reg = rr * 2 + jj;
                    float gi = d[p][mt][0][reg];
                    float gf = d[p][mt][1][reg];
                    float gg = d[p][mt][2][reg];
                    float go = d[p][mt][3][reg];
                    int ci = ((p * 2 + mt) * 2 + rr) * 2 + jj;
                    float cc = sigf(gf) * c[ci] + sigf(gi) * tanha(gg);
                    c[ci] = cc;
                    hv[jj] = sigf(go) * tanha(cc);
                }
                int r = m0 + 16 * mt + (l >> 2) + 8 * rr;
                int j0 = js + 2 * (l & 3);
                *(__half2*)(HBw[nxt] + r * 144 + j0 * 2) =
                    __halves2half2(__float2half(hv[0]), __float2half(hv[1]));
            }
        }
        GBAR(g);   // only this M-group needs to agree
    }

    // final h(7) pack: needs both groups' rows visible -> full sync
    __syncthreads();
    {
        uint32_t* gdst = g_h1 + ((size_t)blockIdx.x * T_STEPS + 7) * 2048;
#pragma unroll
        for (int q = 0; q < 2; q++) {
            int iu = q * 1024 + tid * 4;
            int m = iu >> 5, jh = (iu & 31) * 2;
            *(uint4*)(gdst + iu) = *(const uint4*)(HBc[0] + m * 144 + jh * 2);
        }
    }
}

// ============================ kernel 2: layer 2 + FC ============================
__global__ void __launch_bounds__(THREADS, 2) lstm_l2(
    const float* __restrict__ Wih1, const float* __restrict__ Whh1,
    const float* __restrict__ bih1, const float* __restrict__ bhh1,
    const float* __restrict__ Wfc, const float* __restrict__ bfc,
    float* __restrict__ out)
{
    extern __shared__ char sm[];
    const int tid = threadIdx.x;

    for (int i = tid; i < K2_SMEM / 4; i += THREADS) ((uint32_t*)sm)[i] = 0;
    __syncthreads();

    for (int idx = tid; idx < 16384; idx += THREADS) {
        int r = idx >> 6, k = idx & 63;
        *(__half*)(sm + K2_W2 + r * 272 + k * 2) = __float2half(Wih1[idx]);
        *(__half*)(sm + K2_W2 + r * 272 + (64 + k) * 2) = __float2half(Whh1[idx]);
    }
    if (tid < 256) ((float*)(sm + K2_BIAS))[tid] = bih1[tid] + bhh1[tid];
    if (tid < 64)  ((float*)(sm + K2_WFC))[tid] = Wfc[tid];

    const int l = tid & 31, w = tid >> 5, mw = w >> 2, nw = w & 3;
    const int g = tid >> 7;
    const int lt = tid & 127;
    const int m0 = mw * 32;
    const uint32_t sb = smem_u32(sm);
    const int rowA = l & 15;
    const int colA = (l & 16) ? 16 : 0;
    const int rowB2 = (l & 7) + ((l >> 4) & 1) * 64;
    const int colB2 = ((l >> 3) & 1) * 16;
    const size_t gb = (size_t)blockIdx.x * 64;
    const float* biasp = (const float*)(sm + K2_BIAS);
    const float* wfcp  = (const float*)(sm + K2_WFC);
    float* scr = (float*)(sm + K2_SCR);

    float c[16];
#pragma unroll
    for (int i = 0; i < 16; i++) c[i] = 0.0f;

    const uint32_t* gsrc_base = g_h1 + (size_t)blockIdx.x * T_STEPS * 2048;

    // prefetch + stage h1(0) into H1A (own group's words)
    uint4 pf[2];
#pragma unroll
    for (int q = 0; q < 2; q++)
        pf[q] = *(const uint4*)(gsrc_base + g * 1024 + q * 512 + lt * 4);
#pragma unroll
    for (int q = 0; q < 2; q++) {
        int iu = g * 1024 + q * 512 + lt * 4;
        int m = iu >> 5, jh = (iu & 31) * 2;
        *(uint4*)(sm + K2_H1A + m * 144 + jh * 2) = pf[q];
    }
    __syncthreads();

    const uint32_t H1B_[2] = { sb + K2_H1A, sb + K2_H1B };
    const uint32_t H2B_[2] = { sb + K2_H2A, sb + K2_H2B };
    char* H1w[2] = { sm + K2_H1A, sm + K2_H1B };
    char* H2w[2] = { sm + K2_H2A, sm + K2_H2B };

    for (int t = 0; t < T_STEPS; t++) {
        const int cur = t & 1, nxt = cur ^ 1;

        // prefetch h1(t+1) (own group's words)
        if (t < T_STEPS - 1) {
            const uint32_t* gsrc = gsrc_base + (size_t)(t + 1) * 2048;
#pragma unroll
            for (int q = 0; q < 2; q++)
                pf[q] = *(const uint4*)(gsrc + g * 1024 + q * 512 + lt * 4);
        }

        // ---- MMA phase ----
        float d[2][2][4][4];
#pragma unroll
        for (int p = 0; p < 2; p++) {
            const int js = nw * 16 + p * 8;
#pragma unroll
            for (int gg2 = 0; gg2 < 4; gg2++) {
                float2 bv = *(const float2*)(biasp + gg2 * 64 + js + 2 * (l & 3));
#pragma unroll
                for (int mt = 0; mt < 2; mt++) {
                    d[p][mt][gg2][0] = bv.x; d[p][mt][gg2][1] = bv.y;
                    d[p][mt][gg2][2] = bv.x; d[p][mt][gg2][3] = bv.y;
                }
            }
        }
#pragma unroll
        for (int kt = 0; kt < 8; kt++) {
            const int k0 = kt * 16;
            const uint32_t abase = (kt < 4) ? H1B_[cur] : H2B_[cur];
            const int ka = (kt < 4) ? k0 : (k0 - 64);
            uint32_t ah0[4], ah1[4];
            ldsm_x4(ah0, abase + (uint32_t)(m0 + rowA) * 144 + ka * 2 + colA);
            ldsm_x4(ah1, abase + (uint32_t)(m0 + 16 + rowA) * 144 + ka * 2 + colA);
#pragma unroll
            for (int p = 0; p < 2; p++) {
                const int js = nw * 16 + p * 8;
                uint32_t b01[4], b23[4];
                ldsm_x4(b01, sb + K2_W2 + (uint32_t)(js + rowB2) * 272 + k0 * 2 + colB2);
                ldsm_x4(b23, sb + K2_W2 + (uint32_t)(128 + js + rowB2) * 272 + k0 * 2 + colB2);
                mma16816(d[p][0][0], ah0, b01);     mma16816(d[p][0][1], ah0, b01 + 2);
                mma16816(d[p][0][2], ah0, b23);     mma16816(d[p][0][3], ah0, b23 + 2);
                mma16816(d[p][1][0], ah1, b01);     mma16816(d[p][1][1], ah1, b01 + 2);
                mma16816(d[p][1][2], ah1, b23);     mma16816(d[p][1][3], ah1, b23 + 2);
            }
        }

        // unpack prefetched h1(t+1) into H1[nxt] (own group's rows)
        if (t < T_STEPS - 1) {
#pragma unroll
            for (int q = 0; q < 2; q++) {
                int iu = g * 1024 + q * 512 + lt * 4;
                int m = iu >> 5, jh = (iu & 31) * 2;
                *(uint4*)(H1w[nxt] + m * 144 + jh * 2) = pf[q];
            }
        }

        // ---- epilogue: write h2(t) into H2[nxt]; FC on last step ----
#pragma unroll
        for (int p = 0; p < 2; p++) {
            const int js = nw * 16 + p * 8;
#pragma unroll
            for (int mt = 0; mt < 2; mt++)
#pragma unroll
            for (int rr = 0; rr < 2; rr++) {
                float hv[2];
#pragma unroll
                for (int jj = 0; jj < 2; jj++) {
                    int reg = rr * 2 + jj;
                    float gi = d[p][mt][0][reg];
                    float gf = d[p][mt][1][reg];
                    float gg = d[p][mt][2][reg];
                    float go = d[p][mt][3][reg];
                    int ci = ((p * 2 + mt) * 2 + rr) * 2 + jj;
                    float cc = sigf(gf) * c[ci] + sigf(gi) * tanha(gg);
                    c[ci] = cc;
                    hv[jj] = sigf(go) * tanha(cc);
                }
                int r = m0 + 16 * mt + (l >> 2) + 8 * rr;
                int j0 = js + 2 * (l & 3);
                *(__half2*)(H2w[nxt] + r * 144 + j0 * 2) =
                    __halves2half2(__float2half(hv[0]), __float2half(hv[1]));
                if (t == T_STEPS - 1)
                    atomicAdd(scr + r, hv[0] * wfcp[j0] + hv[1] * wfcp[j0 + 1]);
            }
        }
        GBAR(g);
    }

    __syncthreads();   // both groups' scr contributions visible
    if (tid < 64) out[gb + tid] = scr[tid] + bfc[0];
}

extern "C" void kernel_launch(void* const* d_in, const int* in_sizes, int n_in,
                              void* d_out, int out_size)
{
    const float* x    = (const float*)d_in[0];
    const float* Wih0 = (const float*)d_in[1];
    const float* Whh0 = (const float*)d_in[2];
    const float* bih0 = (const float*)d_in[3];
    const float* bhh0 = (const float*)d_in[4];
    const float* Wih1 = (const float*)d_in[5];
    const float* Whh1 = (const float*)d_in[6];
    const float* bih1 = (const float*)d_in[7];
    const float* bhh1 = (const float*)d_in[8];
    const float* Wfc  = (const float*)d_in[9];
    const float* bfc  = (const float*)d_in[10];
    float* out = (float*)d_out;

    cudaFuncSetAttribute(lstm_l1, cudaFuncAttributeMaxDynamicSharedMemorySize, K1_SMEM);
    cudaFuncSetAttribute(lstm_l2, cudaFuncAttributeMaxDynamicSharedMemorySize, K2_SMEM);

    lstm_l1<<<NBLK, THREADS, K1_SMEM>>>(x, Wih0, Whh0, bih0, bhh0);
    lstm_l2<<<NBLK, THREADS, K2_SMEM>>>(Wih1, Whh1, bih1, bhh1, Wfc, bfc, out);
}